// round 11
// baseline (speedup 1.0000x reference)
#include <cuda_runtime.h>
#include <cuda_bf16.h>
#include <cstdint>
#include <math.h>

// Problem: hidden_states (64, 577, 1024) fp32 -> out (64, 289, 1024) fp32
#define Bn   64
#define Tn   577
#define Cn   1024
#define NE   288      // even tokens (2,4,...,576) that merge into odds
#define NO   288      // odd tokens (1,3,...,575) = merge destinations
#define TOUT 289

// ---- static device scratch (no runtime allocation allowed) ----
__device__ float g_anorm [Bn * NE];
__device__ float g_rnormO[Bn * NO];
__device__ float g_scores[(size_t)Bn * NE * NO];  // raw bf16-dot scores [b][i][j]
__device__ int   g_dst   [Bn * NE];
__device__ int   g_off   [Bn * NO];
__device__ int   g_cnt   [Bn * NO];
__device__ int   g_list  [Bn * NE];

// ---------------- helpers ----------------
__device__ __forceinline__ uint32_t smem_u32(const void* p) {
    uint32_t a;
    asm("{ .reg .u64 t; cvta.to.shared.u64 t, %1; cvt.u32.u64 %0, t; }" : "=r"(a) : "l"(p));
    return a;
}
__device__ __forceinline__ void ldm_x4(uint32_t* r, uint32_t addr) {
    asm volatile("ldmatrix.sync.aligned.m8n8.x4.shared.b16 {%0,%1,%2,%3}, [%4];"
        : "=r"(r[0]), "=r"(r[1]), "=r"(r[2]), "=r"(r[3]) : "r"(addr));
}
__device__ __forceinline__ void ldm_x2(uint32_t* r, uint32_t addr) {
    asm volatile("ldmatrix.sync.aligned.m8n8.x2.shared.b16 {%0,%1}, [%2];"
        : "=r"(r[0]), "=r"(r[1]) : "r"(addr));
}
__device__ __forceinline__ void mma_bf16(float* c, const uint32_t* a, const uint32_t* bfr) {
    asm volatile("mma.sync.aligned.m16n8k16.row.col.f32.bf16.bf16.f32 "
        "{%0,%1,%2,%3}, {%4,%5,%6,%7}, {%8,%9}, {%0,%1,%2,%3};"
        : "+f"(c[0]), "+f"(c[1]), "+f"(c[2]), "+f"(c[3])
        : "r"(a[0]), "r"(a[1]), "r"(a[2]), "r"(a[3]), "r"(bfr[0]), "r"(bfr[1]));
}
__device__ __forceinline__ uint32_t pk(float x, float y) {
    __nv_bfloat162 h = __floats2bfloat162_rn(x, y);
    return *(uint32_t*)&h;
}

// ---------------- K1: fused fp32->bf16 GEMM + norms (double-buffered smem) ----------------
// Block (jt, it, b): D[96 x 96] = bf16(A) @ bf16(B)^T, fp32 accum. K in 16 chunks of 64.
// Ping-pong smem: one __syncthreads per chunk; LDG of chunk k+1 issued before compute
// on chunk k. Edge blocks (jt==0 / it==0) accumulate norms in a fixed deterministic order.
#define KC   64
#define LDS_STRIDE 72
#define MAT_BYTES  (96 * LDS_STRIDE * 2)     // 13824 B per matrix per buffer
#define DYN_SMEM   (4 * MAT_BYTES)           // A0, A1, B0, B1

__global__ __launch_bounds__(256) void k_gemm(const float* __restrict__ X) {
    extern __shared__ __align__(16) char dsm[];
    const int b = blockIdx.z, it = blockIdx.y, jt = blockIdx.x;
    const int tid = threadIdx.x, wid = tid >> 5, lane = tid & 31;
    const int wm = wid >> 2, wn = wid & 3;           // warp grid 2 x 4

    // Global-load mapping: 96 rows x 8 segments of 8 floats; 768 jobs = 3 x 256
    int rowL[3], segL[3];
    #pragma unroll
    for (int u = 0; u < 3; u++) { const int v = tid + u * 256; rowL[u] = v >> 3; segL[u] = v & 7; }

    const float* Arow[3]; const float* Brow[3];
    #pragma unroll
    for (int u = 0; u < 3; u++) {
        Arow[u] = X + ((size_t)b * Tn + 2 * (it * 96 + rowL[u] + 1)) * Cn + segL[u] * 8;  // even token
        Brow[u] = X + ((size_t)b * Tn + 2 * (jt * 96 + rowL[u]) + 1) * Cn + segL[u] * 8;  // odd token
    }

    const uint32_t base = smem_u32(dsm);             // A0 @0, A1 @13824, B0 @27648, B1 @41472
    // ldmatrix relative byte offsets (within one matrix buffer)
    uint32_t aRel[3], bRel[3];
    #pragma unroll
    for (int s = 0; s < 3; s++)
        aRel[s] = ((wm * 48 + s * 16 + (lane & 15)) * LDS_STRIDE + (lane >> 4) * 8) << 1;
    #pragma unroll
    for (int p = 0; p < 3; p++)
        bRel[p] = ((wn * 24 + p * 8 + (lane & 7)) * LDS_STRIDE + ((lane >> 3) & 1) * 8) << 1;
    const uint32_t stRel = (rowL[0] * LDS_STRIDE + segL[0] * 8) << 1;   // per-u delta = 256*... use per-u below

    float acc[3][3][4];
    #pragma unroll
    for (int s = 0; s < 3; s++)
        #pragma unroll
        for (int p = 0; p < 3; p++)
            #pragma unroll
            for (int e = 0; e < 4; e++) acc[s][p][e] = 0.f;

    float sqa[3] = {0.f, 0.f, 0.f}, sqb[3] = {0.f, 0.f, 0.f};
    const bool doA = (jt == 0), doB = (it == 0);

    float4 pa0[3], pa1[3], pb0[3], pb1[3];
    #pragma unroll
    for (int u = 0; u < 3; u++) {
        pa0[u] = *(const float4*)(Arow[u]);     pa1[u] = *(const float4*)(Arow[u] + 4);
        pb0[u] = *(const float4*)(Brow[u]);     pb1[u] = *(const float4*)(Brow[u] + 4);
    }

    // store chunk 0 -> buffer 0 (+ norms of chunk 0)
    #pragma unroll
    for (int u = 0; u < 3; u++) {
        const uint32_t so = (rowL[u] * LDS_STRIDE + segL[u] * 8) << 1;
        uint4 va, vb;
        va.x = pk(pa0[u].x, pa0[u].y); va.y = pk(pa0[u].z, pa0[u].w);
        va.z = pk(pa1[u].x, pa1[u].y); va.w = pk(pa1[u].z, pa1[u].w);
        vb.x = pk(pb0[u].x, pb0[u].y); vb.y = pk(pb0[u].z, pb0[u].w);
        vb.z = pk(pb1[u].x, pb1[u].y); vb.w = pk(pb1[u].z, pb1[u].w);
        *(uint4*)(dsm + so)                 = va;
        *(uint4*)(dsm + 2 * MAT_BYTES + so) = vb;
        if (doA) sqa[u] += pa0[u].x*pa0[u].x + pa0[u].y*pa0[u].y + pa0[u].z*pa0[u].z + pa0[u].w*pa0[u].w
                         + pa1[u].x*pa1[u].x + pa1[u].y*pa1[u].y + pa1[u].z*pa1[u].z + pa1[u].w*pa1[u].w;
        if (doB) sqb[u] += pb0[u].x*pb0[u].x + pb0[u].y*pb0[u].y + pb0[u].z*pb0[u].z + pb0[u].w*pb0[u].w
                         + pb1[u].x*pb1[u].x + pb1[u].y*pb1[u].y + pb1[u].z*pb1[u].z + pb1[u].w*pb1[u].w;
    }
    __syncthreads();

    #pragma unroll 1
    for (int kt = 0; kt < Cn / KC; kt++) {
        const uint32_t sel = (kt & 1) * MAT_BYTES;
        // issue next chunk's LDGs (hidden behind compute)
        if (kt < Cn / KC - 1) {
            const int k0 = (kt + 1) * KC;
            #pragma unroll
            for (int u = 0; u < 3; u++) {
                pa0[u] = *(const float4*)(Arow[u] + k0);     pa1[u] = *(const float4*)(Arow[u] + k0 + 4);
                pb0[u] = *(const float4*)(Brow[u] + k0);     pb1[u] = *(const float4*)(Brow[u] + k0 + 4);
            }
        }
        // compute on buffer sel
        #pragma unroll
        for (int step = 0; step < KC / 16; step++) {
            uint32_t aF[3][4], bF[3][2];
            #pragma unroll
            for (int s = 0; s < 3; s++) ldm_x4(aF[s], base + sel + aRel[s] + step * 32);
            #pragma unroll
            for (int p = 0; p < 3; p++) ldm_x2(bF[p], base + 2 * MAT_BYTES + sel + bRel[p] + step * 32);
            #pragma unroll
            for (int s = 0; s < 3; s++)
                #pragma unroll
                for (int p = 0; p < 3; p++) mma_bf16(acc[s][p], aF[s], bF[p]);
        }
        // store next chunk -> other buffer (+ norms)
        if (kt < Cn / KC - 1) {
            const uint32_t osel = ((kt + 1) & 1) * MAT_BYTES;
            #pragma unroll
            for (int u = 0; u < 3; u++) {
                const uint32_t so = (rowL[u] * LDS_STRIDE + segL[u] * 8) << 1;
                uint4 va, vb;
                va.x = pk(pa0[u].x, pa0[u].y); va.y = pk(pa0[u].z, pa0[u].w);
                va.z = pk(pa1[u].x, pa1[u].y); va.w = pk(pa1[u].z, pa1[u].w);
                vb.x = pk(pb0[u].x, pb0[u].y); vb.y = pk(pb0[u].z, pb0[u].w);
                vb.z = pk(pb1[u].x, pb1[u].y); vb.w = pk(pb1[u].z, pb1[u].w);
                *(uint4*)(dsm + osel + so)                 = va;
                *(uint4*)(dsm + 2 * MAT_BYTES + osel + so) = vb;
                if (doA) sqa[u] += pa0[u].x*pa0[u].x + pa0[u].y*pa0[u].y + pa0[u].z*pa0[u].z + pa0[u].w*pa0[u].w
                                 + pa1[u].x*pa1[u].x + pa1[u].y*pa1[u].y + pa1[u].z*pa1[u].z + pa1[u].w*pa1[u].w;
                if (doB) sqb[u] += pb0[u].x*pb0[u].x + pb0[u].y*pb0[u].y + pb0[u].z*pb0[u].z + pb0[u].w*pb0[u].w
                                 + pb1[u].x*pb1[u].x + pb1[u].y*pb1[u].y + pb1[u].z*pb1[u].z + pb1[u].w*pb1[u].w;
            }
        }
        __syncthreads();
    }

    // ---- norms: 8-lane tree (lanes sharing a row are contiguous lane>>3 groups) ----
    if (doA) {
        #pragma unroll
        for (int u = 0; u < 3; u++) {
            float s = sqa[u];
            #pragma unroll
            for (int o = 1; o < 8; o <<= 1) s += __shfl_xor_sync(0xffffffffu, s, o);
            if ((lane & 7) == 0) g_anorm[b * NE + it * 96 + rowL[u]] = sqrtf(s);
        }
    }
    if (doB) {
        #pragma unroll
        for (int u = 0; u < 3; u++) {
            float s = sqb[u];
            #pragma unroll
            for (int o = 1; o < 8; o <<= 1) s += __shfl_xor_sync(0xffffffffu, s, o);
            if ((lane & 7) == 0) g_rnormO[b * NO + jt * 96 + rowL[u]] = 1.0f / sqrtf(s);
        }
    }

    // ---- epilogue: write raw scores (row-major [b][i][j]) ----
    float* sc = g_scores + ((size_t)b * NE + it * 96) * NO + jt * 96;
    const int tr = lane >> 2, tc = (lane & 3) * 2;
    #pragma unroll
    for (int s = 0; s < 3; s++) {
        #pragma unroll
        for (int p = 0; p < 3; p++) {
            const int r0 = wm * 48 + s * 16 + tr;
            const int c  = wn * 24 + p * 8 + tc;
            *(float2*)(sc + (size_t)r0 * NO + c)       = make_float2(acc[s][p][0], acc[s][p][1]);
            *(float2*)(sc + (size_t)(r0 + 8) * NO + c) = make_float2(acc[s][p][2], acc[s][p][3]);
        }
    }
}

// ---------------- K2: candidate filter + exact fp32 re-verify (singleton fast path) ----------------
// One warp per (b, i). Window [max - 2B, max], B = 0.006*|a_i| (rigorous bound 0.0041*|a_i|).
// If the candidate set is a singleton, the bound PROVES it is the exact argmax -> no
// verification needed (no a_i load, no exact dot). Otherwise re-verify exactly in fp32,
// ascending j, strict '>' tie-break (identical decisions to the passing kernel).
__device__ __forceinline__ float exact_score(const float4 a[8], const float* __restrict__ pb,
                                             int lane, float rn) {
    float s = 0.f;
    #pragma unroll
    for (int q = 0; q < 8; q++) {
        const float4 v = *(const float4*)(pb + q * 128 + lane * 4);
        s += a[q].x * v.x + a[q].y * v.y + a[q].z * v.z + a[q].w * v.w;
    }
    #pragma unroll
    for (int o = 16; o > 0; o >>= 1) s += __shfl_xor_sync(0xffffffffu, s, o);
    return s * rn;
}

__global__ __launch_bounds__(256) void k_filter_exact(const float* __restrict__ X) {
    const int w = threadIdx.x >> 5, lane = threadIdx.x & 31;
    const int b = blockIdx.x / 36, sub = blockIdx.x % 36;   // group by b -> L2 reuse of odd rows
    const int i = sub * 8 + w;
    const float* Xb = X + (size_t)b * Tn * Cn;

    // my 9 normalized scores (j = q*32 + lane)
    const float* srow = g_scores + ((size_t)b * NE + i) * NO;
    const float* rnb  = g_rnormO + b * NO;
    float sc[9];
    #pragma unroll
    for (int q = 0; q < 9; q++) sc[q] = srow[q * 32 + lane] * rnb[q * 32 + lane];

    float m = sc[0];
    #pragma unroll
    for (int q = 1; q < 9; q++) m = fmaxf(m, sc[q]);
    #pragma unroll
    for (int o = 16; o > 0; o >>= 1) m = fmaxf(m, __shfl_xor_sync(0xffffffffu, m, o));
    const float thr = m - 0.012f * g_anorm[b * NE + i];

    unsigned masks[9]; int tot = 0;
    #pragma unroll
    for (int q = 0; q < 9; q++) { masks[q] = __ballot_sync(0xffffffffu, sc[q] >= thr); tot += __popc(masks[q]); }

    if (tot == 1) {            // decided by the error bound alone — no exact pass needed
        if (lane == 0) {
            int bj = 0;
            #pragma unroll
            for (int q = 0; q < 9; q++) if (masks[q]) bj = q * 32 + __ffs(masks[q]) - 1;
            g_dst[b * NE + i] = bj;
        }
        return;
    }

    // ambiguous: cache a_i and verify candidates exactly
    float4 a[8];
    const float* pa = Xb + (size_t)(2 * i + 2) * Cn;
    #pragma unroll
    for (int q = 0; q < 8; q++) a[q] = *(const float4*)(pa + q * 128 + lane * 4);

    float best = -3.0e38f; int bj = 0;
    #pragma unroll 1
    for (int q = 0; q < 9; q++) {                 // ascending q, ascending bit => ascending j
        unsigned mask = masks[q];
        while (mask) {
            const int bit = __ffs(mask) - 1;
            mask &= mask - 1;
            const int j = q * 32 + bit;
            const float v = exact_score(a, Xb + (size_t)(2 * j + 1) * Cn, lane, rnb[j]);
            if (v > best) { best = v; bj = j; }   // strict '>' keeps lowest j on tie
        }
    }
    if (lane == 0) g_dst[b * NE + i] = bj;
}

// ---------------- K3: deterministic CSR build (parallel prefix, no atomics) ----------------
__global__ __launch_bounds__(288) void k_build_csr() {
    __shared__ int s_dst[NE];
    __shared__ int s_ws[9];
    const int b = blockIdx.x, t = threadIdx.x, wid = t >> 5, lane = t & 31;
    s_dst[t] = g_dst[b * NE + t];
    __syncthreads();

    int c = 0;
    #pragma unroll 4
    for (int i = 0; i < NE; i++) c += (s_dst[i] == t);

    int inc = c;
    #pragma unroll
    for (int o = 1; o < 32; o <<= 1) {
        const int v = __shfl_up_sync(0xffffffffu, inc, o);
        if (lane >= o) inc += v;
    }
    if (lane == 31) s_ws[wid] = inc;
    __syncthreads();
    int wo = 0;
    #pragma unroll
    for (int wv = 0; wv < 9; wv++) wo += (wv < wid) ? s_ws[wv] : 0;
    const int off = wo + inc - c;   // exclusive prefix

    int wv = 0;
    for (int i = 0; i < NE; i++)
        if (s_dst[i] == t) g_list[b * NE + off + (wv++)] = i;   // ascending i
    g_off[b * NO + t] = off;
    g_cnt[b * NO + t] = c;
}

// ---------------- K4: merge via CSR gather (smem-staged list + pipelined loads) ----------------
__global__ __launch_bounds__(256) void k_merge(const float* __restrict__ X, float* __restrict__ out) {
    __shared__ int s_idx[NE];
    const int b = blockIdx.y, row = blockIdx.x, t = threadIdx.x;
    float* orow = out + ((size_t)b * TOUT + row) * Cn;
    const float* Xb = X + (size_t)b * Tn * Cn;

    if (row == 0) {   // lone unm token = original token 0
        *(float4*)(orow + t * 4) = *(const float4*)(Xb + t * 4);
        return;
    }
    const int j   = row - 1;
    const int off = g_off[b * NO + j];
    const int cnt = g_cnt[b * NO + j];

    for (int s = t; s < cnt; s += 256) s_idx[s] = g_list[b * NE + off + s];
    __syncthreads();

    float4 a = *(const float4*)(Xb + (size_t)(2 * j + 1) * Cn + t * 4);
    if (cnt > 0) {
        float4 nxt = *(const float4*)(Xb + (size_t)(2 * (s_idx[0] + 1)) * Cn + t * 4);
        for (int s = 0; s < cnt; s++) {           // 2-deep pipeline: load s+1 while adding s
            const float4 cur = nxt;
            if (s + 1 < cnt)
                nxt = *(const float4*)(Xb + (size_t)(2 * (s_idx[s + 1] + 1)) * Cn + t * 4);
            a.x += cur.x; a.y += cur.y; a.z += cur.z; a.w += cur.w;
        }
    }
    const float inv = 1.0f / (float)(cnt + 1);
    a.x *= inv; a.y *= inv; a.z *= inv; a.w *= inv;
    *(float4*)(orow + t * 4) = a;
}

// ---------------- launch ----------------
extern "C" void kernel_launch(void* const* d_in, const int* in_sizes, int n_in,
                              void* d_out, int out_size) {
    const float* X = (const float*)d_in[0];
    float* out = (float*)d_out;

    cudaFuncSetAttribute(k_gemm, cudaFuncAttributeMaxDynamicSharedMemorySize, DYN_SMEM);

    k_gemm        <<<dim3(3, 3, Bn), 256, DYN_SMEM>>>(X);
    k_filter_exact<<<Bn * 36, 256>>>(X);
    k_build_csr   <<<Bn, 288>>>();
    k_merge       <<<dim3(TOUT, Bn), 256>>>(X, out);
}